// round 12
// baseline (speedup 1.0000x reference)
#include <cuda_runtime.h>
#include <cuda_bf16.h>

#define CI 16
#define CO 16
#define DEG 16
#define BSROW (1 + DEG)            // 17 ints per bs_slice row

#define THREADS 128
#define NITER 8
#define PTS_BLK 64                 // 8 iters * 8 point-groups
#define GPAD 52                    // s_g row stride (floats): conflict-free

typedef unsigned long long u64;

__device__ __forceinline__ void fma2(u64 &d, u64 a, u64 b) {
    asm("fma.rn.f32x2 %0, %1, %2, %0;" : "+l"(d) : "l"(a), "l"(b));
}
__device__ __forceinline__ float2 upk2(u64 v) {
    float2 f; asm("mov.b64 {%0, %1}, %2;" : "=f"(f.x), "=f"(f.y) : "l"(v)); return f;
}

// out[p,o] = sum_j sum_d radii[p*DEG+j,d] * sum_i W[d,o,i] * features[nbr(p,j),i]
// Factored: g_d[i] = sum_j r_jd * f[nbr_j,i];  out[o] = sum_{d,i} W[d,o,i] * g_d[i]
//
// Phase 1: 16 lanes/pt (q,c4), 4 independent LDG.128 gathers per lane-iter,
//   idx words preloaded at entry, features+radii prefetched at DISTANCE 2
//   (loads for it+2 issued inside iter it, right after the FMA block consumes
//   the slot) -> >= 2 iterations (~600+ cyc) of latency cover for both the
//   L2 feature gather and the DRAM radii stream.
//   shfl_xor(4)/(8) q-reduce, one predicated STS.128 of g.
// Phase 2: point-per-lane-pair, W broadcast-uniform from smem, packed f32x2
//   FMAs, fully coalesced stores.
__global__ __launch_bounds__(THREADS)
void PeriodicConvolutionPrep_fused(
    const float* __restrict__ features,   // [P, CI]
    const float* __restrict__ radii,      // [P*DEG, 3]
    const float* __restrict__ W,          // [3, CO, CI]
    const int*   __restrict__ bs,         // [P, 1+DEG]
    float*       __restrict__ out,        // [P, CO]
    int P)
{
    __shared__ float  s_g[PTS_BLK][GPAD];     // 13.3 KB
    __shared__ float4 s_w2[12][16];           // 3 KB: s_w2[d*4+cq][o] = W[d][o][4cq..+3]

    const int tid   = threadIdx.x;
    const int t16   = tid & 15;
    const int q     = t16 >> 2;
    const int c4    = t16 & 3;
    const int pt    = tid >> 4;
    const int wrp   = tid >> 5;
    const int lane  = tid & 31;
    const int gbase = lane & ~15;

    const int base   = blockIdx.x * PTS_BLK;
    const int nvalid = min(PTS_BLK, P - base);

    // ---- stage W for phase 2 ----
    {
        const float4* w4 = (const float4*)W;
        for (int t = tid; t < 192; t += THREADS) {
            const int kb = t >> 4, o = t & 15;
            const int d = kb >> 2, cq = kb & 3;
            s_w2[kb][o] = __ldg(w4 + (size_t)d * 64 + o * 4 + cq);
        }
    }

    // ---- point ids + preload ALL iterations' index words ----
    int  p[NITER];
    bool valid[NITER];
    int  myv[NITER];
#pragma unroll
    for (int it = 0; it < NITER; it++) {
        int pp = base + it * 8 + pt;
        valid[it] = (pp < P);
        p[it] = valid[it] ? pp : (P - 1);
        myv[it] = __ldg(bs + (size_t)p[it] * BSROW + 1 + t16);
    }

    float4 fpre[2][4];
    float4 rpre[2][3];
    const float4* fb4 = (const float4*)features;

    auto issue_loads = [&](int it, int slot) {
        const int m  = myv[it];
        const int i0 = __shfl_sync(0xffffffffu, m, gbase + 4 * q + 0);
        const int i1 = __shfl_sync(0xffffffffu, m, gbase + 4 * q + 1);
        const int i2 = __shfl_sync(0xffffffffu, m, gbase + 4 * q + 2);
        const int i3 = __shfl_sync(0xffffffffu, m, gbase + 4 * q + 3);
        fpre[slot][0] = __ldg(fb4 + (size_t)i0 * (CI / 4) + c4);
        fpre[slot][1] = __ldg(fb4 + (size_t)i1 * (CI / 4) + c4);
        fpre[slot][2] = __ldg(fb4 + (size_t)i2 * (CI / 4) + c4);
        fpre[slot][3] = __ldg(fb4 + (size_t)i3 * (CI / 4) + c4);
        const float4* rp = (const float4*)(radii + ((size_t)p[it] * DEG + 4 * q) * 3);
        rpre[slot][0] = __ldg(rp + 0);
        rpre[slot][1] = __ldg(rp + 1);
        rpre[slot][2] = __ldg(rp + 2);
    };

    // ---- distance-2 prologue ----
    issue_loads(0, 0);
    issue_loads(1, 1);

    // ================= Phase 1 =================
#pragma unroll
    for (int it = 0; it < NITER; it++) {
        const int slot = it & 1;

        const float4 f0 = fpre[slot][0];
        const float4 f1 = fpre[slot][1];
        const float4 f2 = fpre[slot][2];
        const float4 f3 = fpre[slot][3];
        const float4 rv0 = rpre[slot][0];
        const float4 rv1 = rpre[slot][1];
        const float4 rv2 = rpre[slot][2];
        const float r[12] = { rv0.x, rv0.y, rv0.z, rv0.w, rv1.x, rv1.y,
                              rv1.z, rv1.w, rv2.x, rv2.y, rv2.z, rv2.w };

        float g[12];
#pragma unroll
        for (int d = 0; d < 3; d++) {
            g[d * 4 + 0] = r[0 * 3 + d] * f0.x;
            g[d * 4 + 1] = r[0 * 3 + d] * f0.y;
            g[d * 4 + 2] = r[0 * 3 + d] * f0.z;
            g[d * 4 + 3] = r[0 * 3 + d] * f0.w;
            g[d * 4 + 0] = fmaf(r[1 * 3 + d], f1.x, g[d * 4 + 0]);
            g[d * 4 + 1] = fmaf(r[1 * 3 + d], f1.y, g[d * 4 + 1]);
            g[d * 4 + 2] = fmaf(r[1 * 3 + d], f1.z, g[d * 4 + 2]);
            g[d * 4 + 3] = fmaf(r[1 * 3 + d], f1.w, g[d * 4 + 3]);
            g[d * 4 + 0] = fmaf(r[2 * 3 + d], f2.x, g[d * 4 + 0]);
            g[d * 4 + 1] = fmaf(r[2 * 3 + d], f2.y, g[d * 4 + 1]);
            g[d * 4 + 2] = fmaf(r[2 * 3 + d], f2.z, g[d * 4 + 2]);
            g[d * 4 + 3] = fmaf(r[2 * 3 + d], f2.w, g[d * 4 + 3]);
            g[d * 4 + 0] = fmaf(r[3 * 3 + d], f3.x, g[d * 4 + 0]);
            g[d * 4 + 1] = fmaf(r[3 * 3 + d], f3.y, g[d * 4 + 1]);
            g[d * 4 + 2] = fmaf(r[3 * 3 + d], f3.z, g[d * 4 + 2]);
            g[d * 4 + 3] = fmaf(r[3 * 3 + d], f3.w, g[d * 4 + 3]);
        }

        // slot just consumed -> refill for it+2 (>= 1 full iter + reduce of cover)
        if (it + 2 < NITER)
            issue_loads(it + 2, slot);

        // reduce over q
#pragma unroll
        for (int v = 0; v < 12; v++) g[v] += __shfl_xor_sync(0xffffffffu, g[v], 4);
#pragma unroll
        for (int v = 0; v < 12; v++) g[v] += __shfl_xor_sync(0xffffffffu, g[v], 8);

        if (q < 3 && valid[it])
            *(float4*)&s_g[it * 8 + pt][q * CI + 4 * c4] =
                make_float4(g[q * 4 + 0], g[q * 4 + 1], g[q * 4 + 2], g[q * 4 + 3]);
    }

    __syncthreads();

    // ================= Phase 2: packed f32x2, uniform W =================
    {
        const int p16 = lane & 15;
        const int oh  = lane >> 4;
        const int pL  = wrp * 16 + p16;

        if (pL < nvalid) {
            u64 acc[8];
#pragma unroll
            for (int oo = 0; oo < 8; oo++) acc[oo] = 0ull;

#pragma unroll
            for (int kb = 0; kb < 12; kb++) {
                const ulonglong2 gv = *(const ulonglong2*)&s_g[pL][kb * 4];
#pragma unroll
                for (int oo = 0; oo < 8; oo++) {
                    const ulonglong2 wv = *(const ulonglong2*)&s_w2[kb][oh * 8 + oo];
                    fma2(acc[oo], wv.x, gv.x);
                    fma2(acc[oo], wv.y, gv.y);
                }
            }

            float res[8];
#pragma unroll
            for (int oo = 0; oo < 8; oo++) {
                const float2 f = upk2(acc[oo]);
                res[oo] = f.x + f.y;
            }
            float4* op = (float4*)(out + (size_t)(base + pL) * CO + oh * 8);
            op[0] = make_float4(res[0], res[1], res[2], res[3]);
            op[1] = make_float4(res[4], res[5], res[6], res[7]);
        }
    }
}

extern "C" void kernel_launch(void* const* d_in, const int* in_sizes, int n_in,
                              void* d_out, int out_size) {
    const float* features = (const float*)d_in[0];
    const float* radii    = (const float*)d_in[1];
    const float* W        = (const float*)d_in[2];
    const int*   bs       = (const int*)d_in[3];
    float*       out      = (float*)d_out;

    const int P = in_sizes[0] / CI;
    const int blocks = (P + PTS_BLK - 1) / PTS_BLK;   // 625 for P=40000
    PeriodicConvolutionPrep_fused<<<blocks, THREADS>>>(features, radii, W, bs, out, P);
}